// round 6
// baseline (speedup 1.0000x reference)
#include <cuda_runtime.h>
#include <math.h>

// Problem constants
#define BB   8
#define CC   256
#define TT   4096
#define KK   1024
#define NN   (BB*TT)          // 32768 rows
#define TM   32               // rows per block
#define NTH  256
#define EPSF 1e-10f

#define ZQ_SIZE   (BB*CC*TT)                  // 8388608
#define PROB_SIZE (NN*KK)                     // 33554432
#define TOTAL_OUT (ZQ_SIZE + 1 + 2*PROB_SIZE + KK)  // 75498497

// Shared memory layout (in floats)
#define SM_L   0                         // logits/encodings: 32*1024      = 32768
#define SM_ZS  (TM*KK)                   // z tile / zq staging: 32*257    =  8224
#define SM_BS  (SM_ZS + TM*257)          // book chunk: max(128*68,64*260) = 16640
#define SM_ZN  (SM_BS + 16640)           // z row norms: 32
#define SM_RA  (SM_ZN + TM)              // per-row lse / inv-sum: 32
#define SM_TOT (SM_RA + TM)              // 57696 floats = 230784 bytes

// Device scratch (statically allocated — no runtime allocation)
__device__ float g_bnorm[KK];
__device__ float g_mp_partial[(NN/TM) * KK];   // 4 MB

__device__ __forceinline__ float warp_max(float v) {
    #pragma unroll
    for (int o = 16; o > 0; o >>= 1) v = fmaxf(v, __shfl_xor_sync(0xffffffffu, v, o));
    return v;
}
__device__ __forceinline__ float warp_sum(float v) {
    #pragma unroll
    for (int o = 16; o > 0; o >>= 1) v += __shfl_xor_sync(0xffffffffu, v, o);
    return v;
}
__device__ __forceinline__ float gumbelf(float uu) {
    return -__logf(-__logf(uu + EPSF) + EPSF);
}

// ---------------------------------------------------------------------------
// Book row squared norms
// ---------------------------------------------------------------------------
__global__ void bnorm_kernel(const float* __restrict__ book) {
    int gw   = (blockIdx.x * blockDim.x + threadIdx.x) >> 5;
    int lane = threadIdx.x & 31;
    if (gw >= KK) return;
    const float* row = book + (size_t)gw * CC;
    float s = 0.f;
    #pragma unroll
    for (int c = lane; c < CC; c += 32) { float v = row[c]; s = fmaf(v, v, s); }
    s = warp_sum(s);
    if (lane == 0) g_bnorm[gw] = s;
}

// ---------------------------------------------------------------------------
// Deterministic mean_prob reduction (sequential per-k order)
// ---------------------------------------------------------------------------
__global__ void mp_reduce_kernel(float* __restrict__ mean_out) {
    int k = blockIdx.x * blockDim.x + threadIdx.x;   // 4 blocks * 256 = 1024
    float s = 0.f;
    #pragma unroll 8
    for (int b = 0; b < NN/TM; ++b) s += g_mp_partial[(size_t)b * KK + k];
    mean_out[k] = s;
}

// ---------------------------------------------------------------------------
// Fused main kernel: 1 block = 32 rows. 1024 blocks.
// ---------------------------------------------------------------------------
__global__ __launch_bounds__(NTH, 1)
void gvq_main(const float* __restrict__ z, const float* __restrict__ book,
              const float* __restrict__ lpq, const float* __restrict__ u,
              float* __restrict__ zq_out,
              float* __restrict__ prob_out, float* __restrict__ logp_out,
              float* __restrict__ pq_out, int full)
{
    extern __shared__ float sm[];
    float* L  = sm + SM_L;
    float* zs = sm + SM_ZS;
    float* bs = sm + SM_BS;
    float* zn = sm + SM_ZN;
    float* ra = sm + SM_RA;

    const int tid  = threadIdx.x;
    const int blk  = blockIdx.x;
    const int n0   = blk * TM;
    const int bb   = blk >> 7;            // 128 blocks per batch
    const int t0   = (blk & 127) * TM;
    const int lane = tid & 31;
    const int warp = tid >> 5;

    const float pq = 0.5f / (1.0f + expf(lpq[0]));
    if (full && blk == 0 && tid == 0) *pq_out = pq;

    // ---- load z tile: zs[r][c] = z[bb, c, t0+r] (coalesced over t) ----
    const float* zb = z + (size_t)bb * CC * TT + t0;
    #pragma unroll
    for (int it = 0; it < 32; ++it) {
        int idx = it * NTH + tid;
        int c = idx >> 5, r = idx & 31;
        zs[r * 257 + c] = zb[(size_t)c * TT + r];
    }
    __syncthreads();

    // ---- z row norms ----
    #pragma unroll
    for (int rr = 0; rr < 4; ++rr) {
        int r = warp * 4 + rr;
        float s = 0.f;
        #pragma unroll
        for (int c = lane; c < CC; c += 32) { float v = zs[r*257 + c]; s = fmaf(v, v, s); }
        s = warp_sum(s);
        if (lane == 0) zn[r] = s;
    }
    __syncthreads();

    // ---- Phase 1: logits = (2*z.b - ||z||^2 - ||b||^2) * pq  -> L[32][1024]
    //      B chunk: 64 k-cols x 128 c (two c-halves), bs[c][kk] pad 68 (16B-aligned rows)
    {
        const int tx = tid & 15;        // k sub-tile of 4
        const int ty = tid >> 4;        // 0..15 -> row pair
        const int r0 = ty * 2;
        const int cl = tid & 127;       // fill: c within half
        const int kh = (tid >> 7) * 32; // fill: kk half

        for (int kc = 0; kc < 16; ++kc) {
            const int kbase = kc * 64;
            float a00=0,a01=0,a02=0,a03=0,a10=0,a11=0,a12=0,a13=0;

            #pragma unroll
            for (int ch = 0; ch < 2; ++ch) {
                __syncthreads();        // previous chunk's bs reads done
                const float* bkp = book + (size_t)(kbase + kh) * CC + ch * 128 + cl;
                #pragma unroll 8
                for (int kk = 0; kk < 32; ++kk)
                    bs[cl * 68 + kh + kk] = bkp[(size_t)kk * CC];
                __syncthreads();

                const float* zr0 = zs + r0 * 257 + ch * 128;
                const float* zr1 = zr0 + 257;
                #pragma unroll 4
                for (int c = 0; c < 128; ++c) {
                    float z0 = zr0[c];
                    float z1 = zr1[c];
                    float4 bv = *reinterpret_cast<const float4*>(&bs[c*68 + tx*4]);
                    a00 = fmaf(z0, bv.x, a00); a01 = fmaf(z0, bv.y, a01);
                    a02 = fmaf(z0, bv.z, a02); a03 = fmaf(z0, bv.w, a03);
                    a10 = fmaf(z1, bv.x, a10); a11 = fmaf(z1, bv.y, a11);
                    a12 = fmaf(z1, bv.z, a12); a13 = fmaf(z1, bv.w, a13);
                }
            }
            int k0 = kbase + tx * 4;
            float zn0 = zn[r0], zn1 = zn[r0+1];
            float bn0 = g_bnorm[k0], bn1 = g_bnorm[k0+1];
            float bn2 = g_bnorm[k0+2], bn3 = g_bnorm[k0+3];
            L[ r0   *KK + k0+0] = (2.f*a00 - zn0 - bn0) * pq;
            L[ r0   *KK + k0+1] = (2.f*a01 - zn0 - bn1) * pq;
            L[ r0   *KK + k0+2] = (2.f*a02 - zn0 - bn2) * pq;
            L[ r0   *KK + k0+3] = (2.f*a03 - zn0 - bn3) * pq;
            L[(r0+1)*KK + k0+0] = (2.f*a10 - zn1 - bn0) * pq;
            L[(r0+1)*KK + k0+1] = (2.f*a11 - zn1 - bn1) * pq;
            L[(r0+1)*KK + k0+2] = (2.f*a12 - zn1 - bn2) * pq;
            L[(r0+1)*KK + k0+3] = (2.f*a13 - zn1 - bn3) * pq;
        }
    }
    __syncthreads();

    // ---- Phase 2: softmax stats + prob / log_prob / mean_prob partials ----
    if (full) {
        #pragma unroll
        for (int rr = 0; rr < 4; ++rr) {
            int r = warp * 4 + rr;
            const float* Lr = L + r * KK;
            float m = __int_as_float(0xff800000);
            #pragma unroll
            for (int kb = 0; kb < 8; ++kb) {
                float4 v = *reinterpret_cast<const float4*>(Lr + kb*128 + lane*4);
                m = fmaxf(m, fmaxf(fmaxf(v.x, v.y), fmaxf(v.z, v.w)));
            }
            m = warp_max(m);
            float s = 0.f;
            #pragma unroll
            for (int kb = 0; kb < 8; ++kb) {
                float4 v = *reinterpret_cast<const float4*>(Lr + kb*128 + lane*4);
                s += __expf(v.x - m) + __expf(v.y - m) + __expf(v.z - m) + __expf(v.w - m);
            }
            s = warp_sum(s);
            if (lane == 0) ra[r] = m + __logf(s);    // logsumexp
        }
        __syncthreads();

        const float invN = 1.0f / (float)NN;
        #pragma unroll
        for (int j = 0; j < 4; ++j) {
            int k = tid + j * 256;
            float mp = 0.f;
            #pragma unroll 8
            for (int r = 0; r < TM; ++r) {
                float lg = L[r*KK + k];
                float lp = lg - ra[r];
                float p  = __expf(lp);
                prob_out[(size_t)(n0 + r) * KK + k] = p;
                logp_out[(size_t)(n0 + r) * KK + k] = lp;
                mp += p;
            }
            g_mp_partial[(size_t)blk * KK + k] = mp * invN;
        }
        __syncthreads();
    }

    // ---- Phase 3: Gumbel + temperature softmax (unnormalized), in-place in L ----
    #pragma unroll
    for (int rr = 0; rr < 4; ++rr) {
        int r = warp * 4 + rr;
        const float* ur = u + (size_t)(n0 + r) * KK;
        float* Lr = L + r * KK;
        float m = __int_as_float(0xff800000);
        #pragma unroll
        for (int kb = 0; kb < 8; ++kb) {
            float4 uv = *reinterpret_cast<const float4*>(ur + kb*128 + lane*4);
            float4 lv = *reinterpret_cast<float4*>(Lr + kb*128 + lane*4);
            lv.x += gumbelf(uv.x); lv.y += gumbelf(uv.y);
            lv.z += gumbelf(uv.z); lv.w += gumbelf(uv.w);
            *reinterpret_cast<float4*>(Lr + kb*128 + lane*4) = lv;
            m = fmaxf(m, fmaxf(fmaxf(lv.x, lv.y), fmaxf(lv.z, lv.w)));
        }
        m = warp_max(m);
        float s = 0.f;
        #pragma unroll
        for (int kb = 0; kb < 8; ++kb) {
            float4 lv = *reinterpret_cast<float4*>(Lr + kb*128 + lane*4);
            lv.x = __expf(2.0f * (lv.x - m));   // /TEMPERATURE(0.5) == *2
            lv.y = __expf(2.0f * (lv.y - m));
            lv.z = __expf(2.0f * (lv.z - m));
            lv.w = __expf(2.0f * (lv.w - m));
            *reinterpret_cast<float4*>(Lr + kb*128 + lane*4) = lv;
            s += lv.x + lv.y + lv.z + lv.w;
        }
        s = warp_sum(s);
        if (lane == 0) ra[r] = 1.0f / s;
    }

    // ---- Phase 4: z_q = (enc @ book) * inv_sum
    //      bs[kk][c] pad 260 (16B-aligned rows); thread covers c in
    //      {tx*4..+3} and {128+tx*4..+3}  -> conflict-free aligned float4
    {
        const int tx = tid & 31;
        const int ty = tid >> 5;        // warp -> 4 rows
        const int r0 = ty * 4;
        float acc[4][8];
        #pragma unroll
        for (int i = 0; i < 4; ++i)
            #pragma unroll
            for (int j = 0; j < 8; ++j) acc[i][j] = 0.f;

        for (int kc = 0; kc < 16; ++kc) {
            const int kbase = kc * 64;
            __syncthreads();    // orders Phase-3 ra/L writes on first iter, bs reuse after
            #pragma unroll 8
            for (int it = 0; it < 64; ++it) {
                int idx = it * NTH + tid;
                int kk = idx >> 8, c = idx & 255;
                bs[kk * 260 + c] = book[(size_t)(kbase + kk) * CC + c];
            }
            __syncthreads();
            #pragma unroll 2
            for (int kk = 0; kk < 64; ++kk) {
                float e0 = L[(r0+0)*KK + kbase + kk];
                float e1 = L[(r0+1)*KK + kbase + kk];
                float e2 = L[(r0+2)*KK + kbase + kk];
                float e3 = L[(r0+3)*KK + kbase + kk];
                float4 b0 = *reinterpret_cast<const float4*>(&bs[kk*260 + tx*4]);
                float4 b1 = *reinterpret_cast<const float4*>(&bs[kk*260 + 128 + tx*4]);
                acc[0][0]=fmaf(e0,b0.x,acc[0][0]); acc[0][1]=fmaf(e0,b0.y,acc[0][1]);
                acc[0][2]=fmaf(e0,b0.z,acc[0][2]); acc[0][3]=fmaf(e0,b0.w,acc[0][3]);
                acc[0][4]=fmaf(e0,b1.x,acc[0][4]); acc[0][5]=fmaf(e0,b1.y,acc[0][5]);
                acc[0][6]=fmaf(e0,b1.z,acc[0][6]); acc[0][7]=fmaf(e0,b1.w,acc[0][7]);
                acc[1][0]=fmaf(e1,b0.x,acc[1][0]); acc[1][1]=fmaf(e1,b0.y,acc[1][1]);
                acc[1][2]=fmaf(e1,b0.z,acc[1][2]); acc[1][3]=fmaf(e1,b0.w,acc[1][3]);
                acc[1][4]=fmaf(e1,b1.x,acc[1][4]); acc[1][5]=fmaf(e1,b1.y,acc[1][5]);
                acc[1][6]=fmaf(e1,b1.z,acc[1][6]); acc[1][7]=fmaf(e1,b1.w,acc[1][7]);
                acc[2][0]=fmaf(e2,b0.x,acc[2][0]); acc[2][1]=fmaf(e2,b0.y,acc[2][1]);
                acc[2][2]=fmaf(e2,b0.z,acc[2][2]); acc[2][3]=fmaf(e2,b0.w,acc[2][3]);
                acc[2][4]=fmaf(e2,b1.x,acc[2][4]); acc[2][5]=fmaf(e2,b1.y,acc[2][5]);
                acc[2][6]=fmaf(e2,b1.z,acc[2][6]); acc[2][7]=fmaf(e2,b1.w,acc[2][7]);
                acc[3][0]=fmaf(e3,b0.x,acc[3][0]); acc[3][1]=fmaf(e3,b0.y,acc[3][1]);
                acc[3][2]=fmaf(e3,b0.z,acc[3][2]); acc[3][3]=fmaf(e3,b0.w,acc[3][3]);
                acc[3][4]=fmaf(e3,b1.x,acc[3][4]); acc[3][5]=fmaf(e3,b1.y,acc[3][5]);
                acc[3][6]=fmaf(e3,b1.z,acc[3][6]); acc[3][7]=fmaf(e3,b1.w,acc[3][7]);
            }
        }
        __syncthreads();
        // stage scaled z_q tile into zs (z tile no longer needed)
        #pragma unroll
        for (int i = 0; i < 4; ++i) {
            float inv = ra[r0 + i];
            #pragma unroll
            for (int j = 0; j < 4; ++j) {
                zs[(r0+i)*257 + tx*4 + j]       = acc[i][j]   * inv;
                zs[(r0+i)*257 + 128 + tx*4 + j] = acc[i][j+4] * inv;
            }
        }
    }
    __syncthreads();

    // ---- write z_q in [B, C, T] layout (coalesced over t) ----
    float* zqb = zq_out + (size_t)bb * CC * TT + t0;
    #pragma unroll
    for (int it = 0; it < 32; ++it) {
        int idx = it * NTH + tid;
        int c = idx >> 5, r = idx & 31;
        zqb[(size_t)c * TT + r] = zs[r * 257 + c];
    }
}

// ---------------------------------------------------------------------------
extern "C" void kernel_launch(void* const* d_in, const int* in_sizes, int n_in,
                              void* d_out, int out_size) {
    (void)in_sizes; (void)n_in;
    const float* z    = (const float*)d_in[0];
    const float* book = (const float*)d_in[1];
    const float* lpq  = (const float*)d_in[2];
    const float* u    = (const float*)d_in[3];
    float* out = (float*)d_out;

    int full = (out_size >= TOTAL_OUT) ? 1 : 0;
    float* zq   = out;
    float* pq   = full ? (out + ZQ_SIZE)        : nullptr;
    float* prob = full ? (pq + 1)               : nullptr;
    float* logp = full ? (prob + PROB_SIZE)     : nullptr;
    float* mean = full ? (logp + PROB_SIZE)     : nullptr;

    cudaFuncSetAttribute(gvq_main, cudaFuncAttributeMaxDynamicSharedMemorySize,
                         SM_TOT * (int)sizeof(float));

    bnorm_kernel<<<128, 256>>>(book);
    gvq_main<<<NN/TM, NTH, SM_TOT * sizeof(float)>>>(z, book, lpq, u,
                                                     zq, prob, logp, pq, full);
    if (full) mp_reduce_kernel<<<4, 256>>>(mean);
}

// round 8
// speedup vs baseline: 2.4073x; 2.4073x over previous
#include <cuda_runtime.h>
#include <cuda_bf16.h>
#include <cstdint>
#include <math.h>

#define BB   8
#define CC   256
#define TT   4096
#define KK   1024
#define NN   (BB*TT)
#define EPSF 1e-10f

#define ZQ_SIZE   (BB*CC*TT)
#define PROB_SIZE (NN*KK)
#define TOTAL_OUT (ZQ_SIZE + 1 + 2*PROB_SIZE + KK)

// ---------------- device scratch (static — no runtime allocation) ----------
__device__ float    g_bnorm[KK];
__device__ float    g_mp_partial[(NN/32) * KK];        // 4 MB
__device__ float    g_logits[(size_t)NN * KK];         // 128 MB
__device__ uint32_t g_enc_hi[(size_t)NN * KK / 2];     // 64 MB (bf16x2, [n][512w])
__device__ uint32_t g_enc_lo[(size_t)NN * KK / 2];     // 64 MB
__device__ float    g_rinv[NN];
__device__ uint32_t g_book_hi[KK * CC / 2];            // bf16x2 words, [k][128w]
__device__ uint32_t g_book_lo[KK * CC / 2];
__device__ uint32_t g_bookT_hi[CC * KK / 2];           // bf16x2 words, [c][512w]
__device__ uint32_t g_bookT_lo[CC * KK / 2];

// ---------------- helpers ---------------------------------------------------
__device__ __forceinline__ uint32_t smem_u32(const void* p) {
    uint32_t a;
    asm("{ .reg .u64 t; cvta.to.shared.u64 t, %1; cvt.u32.u64 %0, t; }"
        : "=r"(a) : "l"(p));
    return a;
}
__device__ __forceinline__ void ldsm4(uint32_t* r, uint32_t addr) {
    asm volatile("ldmatrix.sync.aligned.m8n8.x4.shared.b16 {%0,%1,%2,%3}, [%4];"
        : "=r"(r[0]), "=r"(r[1]), "=r"(r[2]), "=r"(r[3]) : "r"(addr));
}
__device__ __forceinline__ void mma_bf16(float* d, const uint32_t* a,
                                         uint32_t b0, uint32_t b1) {
    asm volatile("mma.sync.aligned.m16n8k16.row.col.f32.bf16.bf16.f32 "
        "{%0,%1,%2,%3}, {%4,%5,%6,%7}, {%8,%9}, {%0,%1,%2,%3};"
        : "+f"(d[0]), "+f"(d[1]), "+f"(d[2]), "+f"(d[3])
        : "r"(a[0]), "r"(a[1]), "r"(a[2]), "r"(a[3]), "r"(b0), "r"(b1));
}
__device__ __forceinline__ uint32_t pack_bf16x2(float a, float b) {
    __nv_bfloat162 t = __floats2bfloat162_rn(a, b);
    return *reinterpret_cast<uint32_t*>(&t);
}
__device__ __forceinline__ float warp_max(float v) {
    #pragma unroll
    for (int o = 16; o > 0; o >>= 1) v = fmaxf(v, __shfl_xor_sync(0xffffffffu, v, o));
    return v;
}
__device__ __forceinline__ float warp_sum(float v) {
    #pragma unroll
    for (int o = 16; o > 0; o >>= 1) v += __shfl_xor_sync(0xffffffffu, v, o);
    return v;
}
__device__ __forceinline__ float gumbelf(float uu) {
    return -__logf(-__logf(uu + EPSF) + EPSF);
}

// ---------------------------------------------------------------------------
// Prep kernels
// ---------------------------------------------------------------------------
__global__ void bnorm_kernel(const float* __restrict__ book) {
    int gw = (blockIdx.x * blockDim.x + threadIdx.x) >> 5;
    int lane = threadIdx.x & 31;
    if (gw >= KK) return;
    const float* row = book + (size_t)gw * CC;
    float s = 0.f;
    #pragma unroll
    for (int c = lane; c < CC; c += 32) { float v = row[c]; s = fmaf(v, v, s); }
    s = warp_sum(s);
    if (lane == 0) g_bnorm[gw] = s;
}

__global__ void split_book(const float* __restrict__ book) {
    __nv_bfloat16* bh  = reinterpret_cast<__nv_bfloat16*>(g_book_hi);
    __nv_bfloat16* bl  = reinterpret_cast<__nv_bfloat16*>(g_book_lo);
    __nv_bfloat16* bth = reinterpret_cast<__nv_bfloat16*>(g_bookT_hi);
    __nv_bfloat16* btl = reinterpret_cast<__nv_bfloat16*>(g_bookT_lo);
    int idx = blockIdx.x * 256 + threadIdx.x;
    for (int i = idx; i < KK * CC; i += 65536) {
        int k = i >> 8, c = i & 255;
        float v = book[i];
        __nv_bfloat16 h = __float2bfloat16(v);
        __nv_bfloat16 l = __float2bfloat16(v - __bfloat162float(h));
        bh[i] = h; bl[i] = l;
        bth[c * KK + k] = h; btl[c * KK + k] = l;
    }
}

__global__ void mp_reduce_kernel(float* __restrict__ mean_out) {
    int k = blockIdx.x * blockDim.x + threadIdx.x;
    float s = 0.f;
    #pragma unroll 8
    for (int b = 0; b < NN/32; ++b) s += g_mp_partial[(size_t)b * KK + k];
    mean_out[k] = s;
}

// ---------------------------------------------------------------------------
// GEMM1: logits[n][k] = (2*z.b - |z|^2 - |b|^2)*pq  via mma.sync (split bf16)
// 256 blocks x 256 thr; block = 128 rows; book streamed in 64-code chunks.
// smem: zn 0..512 | bn 512..4608 | Ah 4608 | Al 72192 | Bh 139776 | Bl 173568
// A/B row stride 264 bf16 = 528 B (mult 16; 528 mod 128 = 16 -> ldsm clean)
// ---------------------------------------------------------------------------
#define G1_SMEM 207360

__global__ __launch_bounds__(256, 1)
void gemm1(const float* __restrict__ z, const float* __restrict__ lpq) {
    extern __shared__ char smem[];
    float* zn = reinterpret_cast<float*>(smem);
    float* bn = reinterpret_cast<float*>(smem + 512);
    __nv_bfloat16* Ah = reinterpret_cast<__nv_bfloat16*>(smem + 4608);
    __nv_bfloat16* Al = reinterpret_cast<__nv_bfloat16*>(smem + 72192);
    uint32_t* Bhw = reinterpret_cast<uint32_t*>(smem + 139776);
    uint32_t* Blw = reinterpret_cast<uint32_t*>(smem + 173568);
    const uint32_t sb = smem_u32(smem);
    const uint32_t Ah_b = sb + 4608, Al_b = sb + 72192;
    const uint32_t Bh_b = sb + 139776, Bl_b = sb + 173568;

    const int tid = threadIdx.x, lane = tid & 31, wid = tid >> 5;
    const int blk = blockIdx.x;
    const int n0 = blk * 128;
    const int b  = blk >> 5;
    const int t0 = (blk & 31) * 128;

    for (int i = tid; i < KK; i += 256) bn[i] = g_bnorm[i];

    // ---- A fill: thread = channel c, rows = t (coalesced float4 over t) ----
    {
        const float* zp = z + (size_t)b * CC * TT + (size_t)tid * TT + t0;
        #pragma unroll 4
        for (int i = 0; i < 32; ++i) {
            float4 v = *reinterpret_cast<const float4*>(zp + 4*i);
            float vv[4] = {v.x, v.y, v.z, v.w};
            #pragma unroll
            for (int e = 0; e < 4; ++e) {
                int r = 4*i + e;
                __nv_bfloat16 h = __float2bfloat16(vv[e]);
                Ah[r*264 + tid] = h;
                Al[r*264 + tid] = __float2bfloat16(vv[e] - __bfloat162float(h));
            }
        }
    }
    __syncthreads();

    // ---- z row norms from smem (hi+lo) ----
    for (int rr = 0; rr < 16; ++rr) {
        int r = wid * 16 + rr;
        float s = 0.f;
        #pragma unroll
        for (int c = lane; c < CC; c += 32) {
            float v = __bfloat162float(Ah[r*264 + c]) + __bfloat162float(Al[r*264 + c]);
            s = fmaf(v, v, s);
        }
        s = warp_sum(s);
        if (lane == 0) zn[r] = s;
    }

    const float pqv = 0.5f / (1.0f + expf(lpq[0]));

    const int wm = wid >> 1, wn = wid & 1;
    const int r0w = wm * 32, n0w = wn * 32;
    const int g = lane >> 2, tig = lane & 3;
    const int arow  = (lane & 7) + ((lane >> 3) & 1) * 8;
    const int akoff = (lane >> 4) * 8;
    const int brow  = (lane & 7) + (lane >> 4) * 8;
    const int bkoff = ((lane >> 3) & 1) * 8;

    for (int nt = 0; nt < 16; ++nt) {
        __syncthreads();
        // B chunk: 64 codebook rows x 128 words (hi/lo)
        {
            const uint32_t* sh = g_book_hi + (size_t)(nt * 64) * 128;
            const uint32_t* sl = g_book_lo + (size_t)(nt * 64) * 128;
            #pragma unroll 8
            for (int i = tid; i < 8192; i += 256) {
                int kk = i >> 7, w = i & 127;
                Bhw[kk*132 + w] = sh[i];
                Blw[kk*132 + w] = sl[i];
            }
        }
        __syncthreads();

        float acc[2][4][4];
        #pragma unroll
        for (int i = 0; i < 2; ++i)
            #pragma unroll
            for (int j = 0; j < 4; ++j)
                #pragma unroll
                for (int e = 0; e < 4; ++e) acc[i][j][e] = 0.f;

        #pragma unroll 2
        for (int ks = 0; ks < 16; ++ks) {
            uint32_t af[2][4], alf[2][4], bf[2][4], blf[2][4];
            #pragma unroll
            for (int mt = 0; mt < 2; ++mt) {
                uint32_t off = (uint32_t)((r0w + mt*16 + arow) * 264 + ks*16 + akoff) * 2;
                ldsm4(af[mt],  Ah_b + off);
                ldsm4(alf[mt], Al_b + off);
            }
            #pragma unroll
            for (int np = 0; np < 2; ++np) {
                uint32_t off = (uint32_t)((n0w + np*16 + brow) * 264 + ks*16 + bkoff) * 2;
                ldsm4(bf[np],  Bh_b + off);
                ldsm4(blf[np], Bl_b + off);
            }
            #pragma unroll
            for (int mt = 0; mt < 2; ++mt)
                #pragma unroll
                for (int ntile = 0; ntile < 4; ++ntile) {
                    int np = ntile >> 1, sub = (ntile & 1) * 2;
                    mma_bf16(acc[mt][ntile], af[mt],  bf[np][sub],  bf[np][sub+1]);
                    mma_bf16(acc[mt][ntile], af[mt],  blf[np][sub], blf[np][sub+1]);
                    mma_bf16(acc[mt][ntile], alf[mt], bf[np][sub],  bf[np][sub+1]);
                }
        }

        // epilogue: scale + direct float2 stores to g_logits
        #pragma unroll
        for (int mt = 0; mt < 2; ++mt) {
            int r_lo = r0w + mt*16 + g;
            float zn0 = zn[r_lo], zn1 = zn[r_lo + 8];
            #pragma unroll
            for (int ntile = 0; ntile < 4; ++ntile) {
                int col = nt*64 + n0w + ntile*8 + 2*tig;
                float bn0 = bn[col], bn1 = bn[col + 1];
                float2 w0, w1;
                w0.x = (2.f*acc[mt][ntile][0] - zn0 - bn0) * pqv;
                w0.y = (2.f*acc[mt][ntile][1] - zn0 - bn1) * pqv;
                w1.x = (2.f*acc[mt][ntile][2] - zn1 - bn0) * pqv;
                w1.y = (2.f*acc[mt][ntile][3] - zn1 - bn1) * pqv;
                *reinterpret_cast<float2*>(&g_logits[(size_t)(n0 + r_lo) * KK + col]) = w0;
                *reinterpret_cast<float2*>(&g_logits[(size_t)(n0 + r_lo + 8) * KK + col]) = w1;
            }
        }
    }
}

// ---------------------------------------------------------------------------
// Softmax kernel: prob/log_prob/mean partials + Gumbel-exp -> enc (bf16 hi/lo)
// ---------------------------------------------------------------------------
#define SMB_TOT  (32 * KK + 32)

__global__ __launch_bounds__(256, 1)
void gvq_soft(const float* __restrict__ u, const float* __restrict__ lpq,
              float* __restrict__ prob_out, float* __restrict__ logp_out,
              float* __restrict__ pq_out, int full)
{
    extern __shared__ float sm[];
    float* L  = sm;
    float* ra = sm + 32 * KK;

    const int tid = threadIdx.x, blk = blockIdx.x;
    const int n0 = blk * 32;
    const int lane = tid & 31, warp = tid >> 5;

    if (full && blk == 0 && tid == 0)
        *pq_out = 0.5f / (1.0f + expf(lpq[0]));

    #pragma unroll
    for (int it = 0; it < 32; ++it) {
        int idx = it * 256 + tid;
        int r = idx >> 8, kw = idx & 255;
        *reinterpret_cast<float4*>(&L[r * KK + kw * 4]) =
            *reinterpret_cast<const float4*>(&g_logits[(size_t)(n0 + r) * KK + kw * 4]);
    }
    __syncthreads();

    if (full) {
        #pragma unroll
        for (int rr = 0; rr < 4; ++rr) {
            int r = warp * 4 + rr;
            const float* Lr = L + r * KK;
            float m = __int_as_float(0xff800000);
            #pragma unroll
            for (int kb = 0; kb < 8; ++kb) {
                float4 v = *reinterpret_cast<const float4*>(Lr + kb*128 + lane*4);
                m = fmaxf(m, fmaxf(fmaxf(v.x, v.y), fmaxf(v.z, v.w)));
            }
            m = warp_max(m);
            float s = 0.f;
            #pragma unroll
            for (int kb = 0; kb < 8; ++kb) {
                float4 v = *reinterpret_cast<const float4*>(Lr + kb*128 + lane*4);
                s += __expf(v.x - m) + __expf(v.y - m) + __expf(v.z - m) + __expf(v.w - m);
            }
            s = warp_sum(s);
            if (lane == 0) ra[r] = m + __logf(s);
        }
        __syncthreads();

        const float invN = 1.0f / (float)NN;
        #pragma unroll
        for (int j = 0; j < 4; ++j) {
            int k = tid + j * 256;
            float mp = 0.f;
            #pragma unroll 8
            for (int r = 0; r < 32; ++r) {
                float lp = L[r * KK + k] - ra[r];
                float p  = __expf(lp);
                prob_out[(size_t)(n0 + r) * KK + k] = p;
                logp_out[(size_t)(n0 + r) * KK + k] = lp;
                mp += p;
            }
            g_mp_partial[(size_t)blk * KK + k] = mp * invN;
        }
        __syncthreads();
    }

    #pragma unroll
    for (int rr = 0; rr < 4; ++rr) {
        int r = warp * 4 + rr;
        const float* ur = u + (size_t)(n0 + r) * KK;
        float* Lr = L + r * KK;
        float m = __int_as_float(0xff800000);
        #pragma unroll
        for (int kb = 0; kb < 8; ++kb) {
            float4 uv = *reinterpret_cast<const float4*>(ur + kb*128 + lane*4);
            float4 lv = *reinterpret_cast<float4*>(Lr + kb*128 + lane*4);
            lv.x += gumbelf(uv.x); lv.y += gumbelf(uv.y);
            lv.z += gumbelf(uv.z); lv.w += gumbelf(uv.w);
            *reinterpret_cast<float4*>(Lr + kb*128 + lane*4) = lv;
            m = fmaxf(m, fmaxf(fmaxf(lv.x, lv.y), fmaxf(lv.z, lv.w)));
        }
        m = warp_max(m);
        float s = 0.f;
        #pragma unroll
        for (int kb = 0; kb < 8; ++kb) {
            float4 lv = *reinterpret_cast<float4*>(Lr + kb*128 + lane*4);
            float e0 = __expf(2.0f * (lv.x - m));
            float e1 = __expf(2.0f * (lv.y - m));
            float e2 = __expf(2.0f * (lv.z - m));
            float e3 = __expf(2.0f * (lv.w - m));
            s += e0 + e1 + e2 + e3;
            __nv_bfloat16 h0=__float2bfloat16(e0), h1=__float2bfloat16(e1);
            __nv_bfloat16 h2=__float2bfloat16(e2), h3=__float2bfloat16(e3);
            uint2 hv, lvv;
            hv.x  = pack_bf16x2(__bfloat162float(h0), __bfloat162float(h1));
            hv.y  = pack_bf16x2(__bfloat162float(h2), __bfloat162float(h3));
            lvv.x = pack_bf16x2(e0 - __bfloat162float(h0), e1 - __bfloat162float(h1));
            lvv.y = pack_bf16x2(e2 - __bfloat162float(h2), e3 - __bfloat162float(h3));
            size_t wi = (size_t)(n0 + r) * 256 + kb * 32 + lane;
            reinterpret_cast<uint2*>(g_enc_hi)[wi] = hv;
            reinterpret_cast<uint2*>(g_enc_lo)[wi] = lvv;
        }
        s = warp_sum(s);
        if (lane == 0) g_rinv[n0 + r] = 1.0f / s;
    }
}

// ---------------------------------------------------------------------------
// GEMM2: z_q = (enc @ book) * rinv  via mma.sync (split bf16).
// 512 blocks: blk>>1 = 128-row tile, blk&1 = 128-c half. k streamed in 64s.
// smem: rinv 0..512 | Ah 512 | Al 18944 | Bh 37376 | Bl 55808 | (stage @512)
// tile row stride 72 bf16 = 144 B (mult 16; 144 mod 128 = 16 -> ldsm clean)
// ---------------------------------------------------------------------------
#define G2_SMEM 74240

__global__ __launch_bounds__(256, 2)
void gemm2(float* __restrict__ zq_out) {
    extern __shared__ char smem[];
    float* rinv_s = reinterpret_cast<float*>(smem);
    uint32_t* Ahw = reinterpret_cast<uint32_t*>(smem + 512);
    uint32_t* Alw = reinterpret_cast<uint32_t*>(smem + 18944);
    uint32_t* Bhw = reinterpret_cast<uint32_t*>(smem + 37376);
    uint32_t* Blw = reinterpret_cast<uint32_t*>(smem + 55808);
    const uint32_t sb = smem_u32(smem);
    const uint32_t Ah_b = sb + 512, Al_b = sb + 18944;
    const uint32_t Bh_b = sb + 37376, Bl_b = sb + 55808;

    const int tid = threadIdx.x, lane = tid & 31, wid = tid >> 5;
    const int blk = blockIdx.x;
    const int rt = blk >> 1, ch = blk & 1;
    const int n0 = rt * 128;
    const int c0 = ch * 128;
    const int bb = rt >> 5;
    const int t0 = (rt & 31) * 128;

    if (tid < 128) rinv_s[tid] = g_rinv[n0 + tid];

    const int wm = wid >> 2, wn = wid & 3;
    const int r0w = wm * 64, n0w = wn * 32;
    const int g = lane >> 2, tig = lane & 3;
    const int arow  = (lane & 7) + ((lane >> 3) & 1) * 8;
    const int akoff = (lane >> 4) * 8;
    const int brow  = (lane & 7) + (lane >> 4) * 8;
    const int bkoff = ((lane >> 3) & 1) * 8;

    float acc[4][4][4];
    #pragma unroll
    for (int i = 0; i < 4; ++i)
        #pragma unroll
        for (int j = 0; j < 4; ++j)
            #pragma unroll
            for (int e = 0; e < 4; ++e) acc[i][j][e] = 0.f;

    for (int kc = 0; kc < 16; ++kc) {
        __syncthreads();
        // A chunk: enc [128 rows][32 words]
        #pragma unroll 4
        for (int i = tid; i < 4096; i += 256) {
            int r = i >> 5, w = i & 31;
            size_t src = (size_t)(n0 + r) * 512 + kc * 32 + w;
            Ahw[r*36 + w] = g_enc_hi[src];
            Alw[r*36 + w] = g_enc_lo[src];
        }
        // B chunk: bookT [128 c][32 words]
        #pragma unroll 4
        for (int i = tid; i < 4096; i += 256) {
            int c = i >> 5, w = i & 31;
            size_t src = (size_t)(c0 + c) * 512 + kc * 32 + w;
            Bhw[c*36 + w] = g_bookT_hi[src];
            Blw[c*36 + w] = g_bookT_lo[src];
        }
        __syncthreads();

        #pragma unroll
        for (int ks = 0; ks < 4; ++ks) {
            uint32_t af[4][4], alf[4][4], bf[2][4], blf[2][4];
            #pragma unroll
            for (int mt = 0; mt < 4; ++mt) {
                uint32_t off = (uint32_t)((r0w + mt*16 + arow) * 72 + ks*16 + akoff) * 2;
                ldsm4(af[mt],  Ah_b + off);
                ldsm4(alf[mt], Al_b + off);
            }
            #pragma unroll
            for (int np = 0; np < 2; ++np) {
                uint32_t off = (uint32_t)((n0w + np*16 + brow) * 72 + ks*16 + bkoff) * 2;
                ldsm4(bf[np],  Bh_b + off);
                ldsm4(blf[np], Bl_b + off);
            }
            #pragma unroll
            for (int mt = 0; mt < 4; ++mt)
                #pragma unroll
                for (int ntile = 0; ntile < 4; ++ntile) {
                    int np = ntile >> 1, sub = (ntile & 1) * 2;
                    mma_bf16(acc[mt][ntile], af[mt],  bf[np][sub],  bf[np][sub+1]);
                    mma_bf16(acc[mt][ntile], af[mt],  blf[np][sub], blf[np][sub+1]);
                    mma_bf16(acc[mt][ntile], alf[mt], bf[np][sub],  bf[np][sub+1]);
                }
        }
    }

    // ---- epilogue: scale by rinv, stage [t][c] (pad 129), coalesced write ----
    __syncthreads();
    float* stage = reinterpret_cast<float*>(smem + 512);
    #pragma unroll
    for (int mt = 0; mt < 4; ++mt) {
        int t_lo = r0w + mt*16 + g;
        float rv0 = rinv_s[t_lo], rv1 = rinv_s[t_lo + 8];
        #pragma unroll
        for (int ntile = 0; ntile < 4; ++ntile) {
            int c = n0w + ntile*8 + 2*tig;
            stage[t_lo*129 + c]       = acc[mt][ntile][0] * rv0;
            stage[t_lo*129 + c + 1]   = acc[mt][ntile][1] * rv0;
            stage[(t_lo+8)*129 + c]   = acc[mt][ntile][2] * rv1;
            stage[(t_lo+8)*129 + c+1] = acc[mt][ntile][3] * rv1;
        }
    }
    __syncthreads();
    float* zqb = zq_out + (size_t)bb * CC * TT + t0;
    #pragma unroll 8
    for (int i = tid; i < 16384; i += 256) {
        int c = i >> 7, tt = i & 127;
        zqb[(size_t)(c0 + c) * TT + tt] = stage[tt*129 + c];
    }
}

// ---------------------------------------------------------------------------
extern "C" void kernel_launch(void* const* d_in, const int* in_sizes, int n_in,
                              void* d_out, int out_size) {
    (void)in_sizes; (void)n_in;
    const float* z    = (const float*)d_in[0];
    const float* book = (const float*)d_in[1];
    const float* lpq  = (const float*)d_in[2];
    const float* u    = (const float*)d_in[3];
    float* out = (float*)d_out;

    int full = (out_size >= TOTAL_OUT) ? 1 : 0;
    float* zq   = out;
    float* pq   = full ? (out + ZQ_SIZE)    : nullptr;
    float* prob = full ? (pq + 1)           : nullptr;
    float* logp = full ? (prob + PROB_SIZE) : nullptr;
    float* mean = full ? (logp + PROB_SIZE) : nullptr;

    cudaFuncSetAttribute(gemm1,    cudaFuncAttributeMaxDynamicSharedMemorySize, G1_SMEM);
    cudaFuncSetAttribute(gvq_soft, cudaFuncAttributeMaxDynamicSharedMemorySize, SMB_TOT * (int)sizeof(float));
    cudaFuncSetAttribute(gemm2,    cudaFuncAttributeMaxDynamicSharedMemorySize, G2_SMEM);

    bnorm_kernel<<<128, 256>>>(book);
    split_book<<<256, 256>>>(book);
    gemm1<<<256, 256, G1_SMEM>>>(z, lpq);
    gvq_soft<<<1024, 256, SMB_TOT * sizeof(float)>>>(u, lpq, prob, logp, pq, full);
    if (full) mp_reduce_kernel<<<4, 256>>>(mean);
    gemm2<<<512, 256, G2_SMEM>>>(zq);
}

// round 9
// speedup vs baseline: 3.2129x; 1.3346x over previous
#include <cuda_runtime.h>
#include <cuda_fp16.h>
#include <cstdint>
#include <math.h>

#define BB   8
#define CC   256
#define TT   4096
#define KK   1024
#define NN   (BB*TT)
#define EPSF 1e-10f

#define ZQ_SIZE   (BB*CC*TT)
#define PROB_SIZE (NN*KK)
#define TOTAL_OUT (ZQ_SIZE + 1 + 2*PROB_SIZE + KK)

#define SROWS 16                      // rows per softmax block

// ---------------- device scratch (static — no runtime allocation) ----------
__device__ float    g_bnorm[KK];
__device__ float    g_mp_partial[(NN/SROWS) * KK];     // 8 MB
__device__ float    g_mp2[8 * KK];
__device__ float    g_logits[(size_t)NN * KK];         // 128 MB
__device__ uint32_t g_enc_hi[(size_t)NN * KK / 2];     // 64 MB (fp16x2, [n][512w])
__device__ float    g_rinv[NN];
__device__ uint32_t g_book_hi[KK * CC / 2];            // fp16x2 words, [k][128w]
__device__ uint32_t g_book_lo[KK * CC / 2];
__device__ uint32_t g_bookT_hi[CC * KK / 2];           // fp16x2 words, [c][512w]
__device__ uint32_t g_bookT_lo[CC * KK / 2];

// ---------------- helpers ---------------------------------------------------
__device__ __forceinline__ uint32_t smem_u32(const void* p) {
    uint32_t a;
    asm("{ .reg .u64 t; cvta.to.shared.u64 t, %1; cvt.u32.u64 %0, t; }"
        : "=r"(a) : "l"(p));
    return a;
}
__device__ __forceinline__ void ldsm4(uint32_t* r, uint32_t addr) {
    asm volatile("ldmatrix.sync.aligned.m8n8.x4.shared.b16 {%0,%1,%2,%3}, [%4];"
        : "=r"(r[0]), "=r"(r[1]), "=r"(r[2]), "=r"(r[3]) : "r"(addr));
}
__device__ __forceinline__ void mma_f16(float* d, const uint32_t* a,
                                        uint32_t b0, uint32_t b1) {
    asm volatile("mma.sync.aligned.m16n8k16.row.col.f32.f16.f16.f32 "
        "{%0,%1,%2,%3}, {%4,%5,%6,%7}, {%8,%9}, {%0,%1,%2,%3};"
        : "+f"(d[0]), "+f"(d[1]), "+f"(d[2]), "+f"(d[3])
        : "r"(a[0]), "r"(a[1]), "r"(a[2]), "r"(a[3]), "r"(b0), "r"(b1));
}
__device__ __forceinline__ uint32_t pack_h2(float a, float b) {
    __half2 t = __floats2half2_rn(a, b);
    return *reinterpret_cast<uint32_t*>(&t);
}
__device__ __forceinline__ float warp_max(float v) {
    #pragma unroll
    for (int o = 16; o > 0; o >>= 1) v = fmaxf(v, __shfl_xor_sync(0xffffffffu, v, o));
    return v;
}
__device__ __forceinline__ float warp_sum(float v) {
    #pragma unroll
    for (int o = 16; o > 0; o >>= 1) v += __shfl_xor_sync(0xffffffffu, v, o);
    return v;
}
__device__ __forceinline__ float gumbelf(float uu) {
    return -__logf(-__logf(uu + EPSF) + EPSF);
}

// ---------------------------------------------------------------------------
// Prep kernels
// ---------------------------------------------------------------------------
__global__ void bnorm_kernel(const float* __restrict__ book) {
    int gw = (blockIdx.x * blockDim.x + threadIdx.x) >> 5;
    int lane = threadIdx.x & 31;
    if (gw >= KK) return;
    const float* row = book + (size_t)gw * CC;
    float s = 0.f;
    #pragma unroll
    for (int c = lane; c < CC; c += 32) { float v = row[c]; s = fmaf(v, v, s); }
    s = warp_sum(s);
    if (lane == 0) g_bnorm[gw] = s;
}

__global__ void split_book(const float* __restrict__ book) {
    __half* bh  = reinterpret_cast<__half*>(g_book_hi);
    __half* bl  = reinterpret_cast<__half*>(g_book_lo);
    __half* bth = reinterpret_cast<__half*>(g_bookT_hi);
    __half* btl = reinterpret_cast<__half*>(g_bookT_lo);
    int idx = blockIdx.x * 256 + threadIdx.x;
    for (int i = idx; i < KK * CC; i += 65536) {
        int k = i >> 8, c = i & 255;
        float v = book[i];
        __half h = __float2half(v);
        __half l = __float2half(v - __half2float(h));
        bh[i] = h; bl[i] = l;
        bth[c * KK + k] = h; btl[c * KK + k] = l;
    }
}

// 2-stage deterministic mean_prob reduction
__global__ void mp_reduce1() {
    int idx = blockIdx.x * 256 + threadIdx.x;     // 32 blocks -> 8192 threads
    int k = idx & 1023, c = idx >> 10;            // c in 0..7
    float s = 0.f;
    #pragma unroll 8
    for (int b = 0; b < (NN/SROWS)/8; ++b)
        s += g_mp_partial[(size_t)(c * ((NN/SROWS)/8) + b) * KK + k];
    g_mp2[c * KK + k] = s;
}
__global__ void mp_reduce2(float* __restrict__ mean_out) {
    int k = blockIdx.x * 256 + threadIdx.x;
    float s = 0.f;
    #pragma unroll
    for (int c = 0; c < 8; ++c) s += g_mp2[c * KK + k];
    mean_out[k] = s;
}

// ---------------------------------------------------------------------------
// GEMM1: logits[n][k] = (2*zhi.(bhi+blo) - |z|^2 - |b|^2)*pq  (fp16 2-term)
// 256 blocks x 256 thr; block = 128 rows; book streamed in 64-code chunks.
// smem: zn 0..512 | bn 512..4608 | Ah 4608 | Al 72192 (norms only) | Bh 139776 | Bl 173568
// row stride 264 fp16 = 528 B (mult 16; 528 mod 128 = 16 -> ldsm clean)
// ---------------------------------------------------------------------------
#define G1_SMEM 207360

__global__ __launch_bounds__(256, 1)
void gemm1(const float* __restrict__ z, const float* __restrict__ lpq) {
    extern __shared__ char smem[];
    float* zn = reinterpret_cast<float*>(smem);
    float* bn = reinterpret_cast<float*>(smem + 512);
    __half* Ah = reinterpret_cast<__half*>(smem + 4608);
    __half* Al = reinterpret_cast<__half*>(smem + 72192);
    uint32_t* Bhw = reinterpret_cast<uint32_t*>(smem + 139776);
    uint32_t* Blw = reinterpret_cast<uint32_t*>(smem + 173568);
    const uint32_t sb = smem_u32(smem);
    const uint32_t Ah_b = sb + 4608;
    const uint32_t Bh_b = sb + 139776, Bl_b = sb + 173568;

    const int tid = threadIdx.x, lane = tid & 31, wid = tid >> 5;
    const int blk = blockIdx.x;
    const int n0 = blk * 128;
    const int b  = blk >> 5;
    const int t0 = (blk & 31) * 128;

    for (int i = tid; i < KK; i += 256) bn[i] = g_bnorm[i];

    // ---- A fill: thread = channel c, rows = t (coalesced float4 over t) ----
    {
        const float* zp = z + (size_t)b * CC * TT + (size_t)tid * TT + t0;
        #pragma unroll 4
        for (int i = 0; i < 32; ++i) {
            float4 v = *reinterpret_cast<const float4*>(zp + 4*i);
            float vv[4] = {v.x, v.y, v.z, v.w};
            #pragma unroll
            for (int e = 0; e < 4; ++e) {
                int r = 4*i + e;
                __half h = __float2half(vv[e]);
                Ah[r*264 + tid] = h;
                Al[r*264 + tid] = __float2half(vv[e] - __half2float(h));
            }
        }
    }
    __syncthreads();

    // ---- z row norms from smem (hi+lo; Al used only here) ----
    for (int rr = 0; rr < 16; ++rr) {
        int r = wid * 16 + rr;
        float s = 0.f;
        #pragma unroll
        for (int c = lane; c < CC; c += 32) {
            float v = __half2float(Ah[r*264 + c]) + __half2float(Al[r*264 + c]);
            s = fmaf(v, v, s);
        }
        s = warp_sum(s);
        if (lane == 0) zn[r] = s;
    }

    const float pqv = 0.5f / (1.0f + expf(lpq[0]));

    const int wm = wid >> 1, wn = wid & 1;
    const int r0w = wm * 32, n0w = wn * 32;
    const int g = lane >> 2, tig = lane & 3;
    const int arow  = (lane & 7) + ((lane >> 3) & 1) * 8;
    const int akoff = (lane >> 4) * 8;
    const int brow  = (lane & 7) + (lane >> 4) * 8;
    const int bkoff = ((lane >> 3) & 1) * 8;

    for (int nt = 0; nt < 16; ++nt) {
        __syncthreads();
        // B chunk: 64 codebook rows x 128 words (hi/lo)
        {
            const uint32_t* sh = g_book_hi + (size_t)(nt * 64) * 128;
            const uint32_t* sl = g_book_lo + (size_t)(nt * 64) * 128;
            #pragma unroll 8
            for (int i = tid; i < 8192; i += 256) {
                int kk = i >> 7, w = i & 127;
                Bhw[kk*132 + w] = sh[i];
                Blw[kk*132 + w] = sl[i];
            }
        }
        __syncthreads();

        float acc[2][4][4];
        #pragma unroll
        for (int i = 0; i < 2; ++i)
            #pragma unroll
            for (int j = 0; j < 4; ++j)
                #pragma unroll
                for (int e = 0; e < 4; ++e) acc[i][j][e] = 0.f;

        #pragma unroll 2
        for (int ks = 0; ks < 16; ++ks) {
            uint32_t af[2][4], bf[2][4], blf[2][4];
            #pragma unroll
            for (int mt = 0; mt < 2; ++mt) {
                uint32_t off = (uint32_t)((r0w + mt*16 + arow) * 264 + ks*16 + akoff) * 2;
                ldsm4(af[mt], Ah_b + off);
            }
            #pragma unroll
            for (int np = 0; np < 2; ++np) {
                uint32_t off = (uint32_t)((n0w + np*16 + brow) * 264 + ks*16 + bkoff) * 2;
                ldsm4(bf[np],  Bh_b + off);
                ldsm4(blf[np], Bl_b + off);
            }
            #pragma unroll
            for (int mt = 0; mt < 2; ++mt)
                #pragma unroll
                for (int ntile = 0; ntile < 4; ++ntile) {
                    int np = ntile >> 1, sub = (ntile & 1) * 2;
                    mma_f16(acc[mt][ntile], af[mt], bf[np][sub],  bf[np][sub+1]);
                    mma_f16(acc[mt][ntile], af[mt], blf[np][sub], blf[np][sub+1]);
                }
        }

        // epilogue: scale + direct float2 stores to g_logits
        #pragma unroll
        for (int mt = 0; mt < 2; ++mt) {
            int r_lo = r0w + mt*16 + g;
            float zn0 = zn[r_lo], zn1 = zn[r_lo + 8];
            #pragma unroll
            for (int ntile = 0; ntile < 4; ++ntile) {
                int col = nt*64 + n0w + ntile*8 + 2*tig;
                float bn0 = bn[col], bn1 = bn[col + 1];
                float2 w0, w1;
                w0.x = (2.f*acc[mt][ntile][0] - zn0 - bn0) * pqv;
                w0.y = (2.f*acc[mt][ntile][1] - zn0 - bn1) * pqv;
                w1.x = (2.f*acc[mt][ntile][2] - zn1 - bn0) * pqv;
                w1.y = (2.f*acc[mt][ntile][3] - zn1 - bn1) * pqv;
                *reinterpret_cast<float2*>(&g_logits[(size_t)(n0 + r_lo) * KK + col]) = w0;
                *reinterpret_cast<float2*>(&g_logits[(size_t)(n0 + r_lo + 8) * KK + col]) = w1;
            }
        }
    }
}

// ---------------------------------------------------------------------------
// Softmax kernel: prob/log_prob/mean partials + Gumbel-exp -> enc (fp16 hi)
// 2048 blocks x 256 thr; block = 16 rows; L in smem (64 KB) -> 2 CTAs/SM
// ---------------------------------------------------------------------------
#define SMB_TOT  (SROWS * KK + 16)

__global__ __launch_bounds__(256, 2)
void gvq_soft(const float* __restrict__ u, const float* __restrict__ lpq,
              float* __restrict__ prob_out, float* __restrict__ logp_out,
              float* __restrict__ pq_out, int full)
{
    extern __shared__ float sm[];
    float* L  = sm;
    float* ra = sm + SROWS * KK;

    const int tid = threadIdx.x, blk = blockIdx.x;
    const int n0 = blk * SROWS;
    const int lane = tid & 31, warp = tid >> 5;

    if (full && blk == 0 && tid == 0)
        *pq_out = 0.5f / (1.0f + expf(lpq[0]));

    #pragma unroll
    for (int it = 0; it < 16; ++it) {
        int idx = it * 256 + tid;
        int r = idx >> 8, kw = idx & 255;
        *reinterpret_cast<float4*>(&L[r * KK + kw * 4]) =
            *reinterpret_cast<const float4*>(&g_logits[(size_t)(n0 + r) * KK + kw * 4]);
    }
    __syncthreads();

    if (full) {
        #pragma unroll
        for (int rr = 0; rr < 2; ++rr) {
            int r = warp * 2 + rr;
            const float* Lr = L + r * KK;
            float m = __int_as_float(0xff800000);
            #pragma unroll
            for (int kb = 0; kb < 8; ++kb) {
                float4 v = *reinterpret_cast<const float4*>(Lr + kb*128 + lane*4);
                m = fmaxf(m, fmaxf(fmaxf(v.x, v.y), fmaxf(v.z, v.w)));
            }
            m = warp_max(m);
            float s = 0.f;
            #pragma unroll
            for (int kb = 0; kb < 8; ++kb) {
                float4 v = *reinterpret_cast<const float4*>(Lr + kb*128 + lane*4);
                s += __expf(v.x - m) + __expf(v.y - m) + __expf(v.z - m) + __expf(v.w - m);
            }
            s = warp_sum(s);
            if (lane == 0) ra[r] = m + __logf(s);
        }
        __syncthreads();

        const float invN = 1.0f / (float)NN;
        #pragma unroll
        for (int j = 0; j < 4; ++j) {
            int k = tid + j * 256;
            float mp = 0.f;
            #pragma unroll 8
            for (int r = 0; r < SROWS; ++r) {
                float lp = L[r * KK + k] - ra[r];
                float p  = __expf(lp);
                prob_out[(size_t)(n0 + r) * KK + k] = p;
                logp_out[(size_t)(n0 + r) * KK + k] = lp;
                mp += p;
            }
            g_mp_partial[(size_t)blk * KK + k] = mp * invN;
        }
        __syncthreads();
    }

    // Gumbel + temperature-0.5 softmax; emit unnormalized exp as fp16 (hi only)
    #pragma unroll
    for (int rr = 0; rr < 2; ++rr) {
        int r = warp * 2 + rr;
        const float* ur = u + (size_t)(n0 + r) * KK;
        float* Lr = L + r * KK;
        float m = __int_as_float(0xff800000);
        #pragma unroll
        for (int kb = 0; kb < 8; ++kb) {
            float4 uv = *reinterpret_cast<const float4*>(ur + kb*128 + lane*4);
            float4 lv = *reinterpret_cast<float4*>(Lr + kb*128 + lane*4);
            lv.x += gumbelf(uv.x); lv.y += gumbelf(uv.y);
            lv.z += gumbelf(uv.z); lv.w += gumbelf(uv.w);
            *reinterpret_cast<float4*>(Lr + kb*128 + lane*4) = lv;
            m = fmaxf(m, fmaxf(fmaxf(lv.x, lv.y), fmaxf(lv.z, lv.w)));
        }
        m = warp_max(m);
        float s = 0.f;
        #pragma unroll
        for (int kb = 0; kb < 8; ++kb) {
            float4 lv = *reinterpret_cast<float4*>(Lr + kb*128 + lane*4);
            float e0 = __expf(2.0f * (lv.x - m));
            float e1 = __expf(2.0f * (lv.y - m));
            float e2 = __expf(2.0f * (lv.z - m));
            float e3 = __expf(2.0f * (lv.w - m));
            s += e0 + e1 + e2 + e3;
            uint2 hv;
            hv.x = pack_h2(e0, e1);
            hv.y = pack_h2(e2, e3);
            reinterpret_cast<uint2*>(g_enc_hi)[(size_t)(n0 + r) * 256 + kb * 32 + lane] = hv;
        }
        s = warp_sum(s);
        if (lane == 0) g_rinv[n0 + r] = 1.0f / s;
    }
}

// ---------------------------------------------------------------------------
// GEMM2: z_q = (ehi @ (bhi+blo)) * rinv  (fp16 2-term)
// 512 blocks: blk>>1 = 128-row tile, blk&1 = 128-c half. k streamed in 64s.
// smem: rinv 0..512 | Ah 512 (18432) | Bh 18944 | Bl 37376 | stage @512 (66048)
// tile row stride 72 fp16 = 144 B (mult 16; 144 mod 128 = 16 -> ldsm clean)
// ---------------------------------------------------------------------------
#define G2_SMEM 66560

__global__ __launch_bounds__(256, 2)
void gemm2(float* __restrict__ zq_out) {
    extern __shared__ char smem[];
    float* rinv_s = reinterpret_cast<float*>(smem);
    uint32_t* Ahw = reinterpret_cast<uint32_t*>(smem + 512);
    uint32_t* Bhw = reinterpret_cast<uint32_t*>(smem + 18944);
    uint32_t* Blw = reinterpret_cast<uint32_t*>(smem + 37376);
    const uint32_t sb = smem_u32(smem);
    const uint32_t Ah_b = sb + 512;
    const uint32_t Bh_b = sb + 18944, Bl_b = sb + 37376;

    const int tid = threadIdx.x, lane = tid & 31, wid = tid >> 5;
    const int blk = blockIdx.x;
    const int rt = blk >> 1, ch = blk & 1;
    const int n0 = rt * 128;
    const int c0 = ch * 128;
    const int bb = rt >> 5;
    const int t0 = (rt & 31) * 128;

    if (tid < 128) rinv_s[tid] = g_rinv[n0 + tid];

    const int wm = wid >> 2, wn = wid & 3;
    const int r0w = wm * 64, n0w = wn * 32;
    const int g = lane >> 2, tig = lane & 3;
    const int arow  = (lane & 7) + ((lane >> 3) & 1) * 8;
    const int akoff = (lane >> 4) * 8;
    const int brow  = (lane & 7) + (lane >> 4) * 8;
    const int bkoff = ((lane >> 3) & 1) * 8;

    float acc[4][4][4];
    #pragma unroll
    for (int i = 0; i < 4; ++i)
        #pragma unroll
        for (int j = 0; j < 4; ++j)
            #pragma unroll
            for (int e = 0; e < 4; ++e) acc[i][j][e] = 0.f;

    for (int kc = 0; kc < 16; ++kc) {
        __syncthreads();
        // A chunk: enc hi [128 rows][32 words]
        #pragma unroll 4
        for (int i = tid; i < 4096; i += 256) {
            int r = i >> 5, w = i & 31;
            Ahw[r*36 + w] = g_enc_hi[(size_t)(n0 + r) * 512 + kc * 32 + w];
        }
        // B chunk: bookT hi/lo [128 c][32 words]
        #pragma unroll 4
        for (int i = tid; i < 4096; i += 256) {
            int c = i >> 5, w = i & 31;
            size_t src = (size_t)(c0 + c) * 512 + kc * 32 + w;
            Bhw[c*36 + w] = g_bookT_hi[src];
            Blw[c*36 + w] = g_bookT_lo[src];
        }
        __syncthreads();

        #pragma unroll
        for (int ks = 0; ks < 4; ++ks) {
            uint32_t af[4][4], bf[2][4], blf[2][4];
            #pragma unroll
            for (int mt = 0; mt < 4; ++mt) {
                uint32_t off = (uint32_t)((r0w + mt*16 + arow) * 72 + ks*16 + akoff) * 2;
                ldsm4(af[mt], Ah_b + off);
            }
            #pragma unroll
            for (int np = 0; np < 2; ++np) {
                uint32_t off = (uint32_t)((n0w + np*16 + brow) * 72 + ks*16 + bkoff) * 2;
                ldsm4(bf[np],  Bh_b + off);
                ldsm4(blf[np], Bl_b + off);
            }
            #pragma unroll
            for (int mt = 0; mt < 4; ++mt)
                #pragma unroll
                for (int ntile = 0; ntile < 4; ++ntile) {
                    int np = ntile >> 1, sub = (ntile & 1) * 2;
                    mma_f16(acc[mt][ntile], af[mt], bf[np][sub],  bf[np][sub+1]);
                    mma_f16(acc[mt][ntile], af[mt], blf[np][sub], blf[np][sub+1]);
                }
        }
    }

    // ---- epilogue: scale by rinv, stage [t][c] (pad 129), coalesced write ----
    __syncthreads();
    float* stage = reinterpret_cast<float*>(smem + 512);
    #pragma unroll
    for (int mt = 0; mt < 4; ++mt) {
        int t_lo = r0w + mt*16 + g;
        float rv0 = rinv_s[t_lo], rv1 = rinv_s[t_lo + 8];
        #pragma unroll
        for (int ntile = 0; ntile < 4; ++ntile) {
            int c = n0w + ntile*8 + 2*tig;
            stage[t_lo*129 + c]       = acc[mt][ntile][0] * rv0;
            stage[t_lo*129 + c + 1]   = acc[mt][ntile][1] * rv0;
            stage[(t_lo+8)*129 + c]   = acc[mt][ntile][2] * rv1;
            stage[(t_lo+8)*129 + c+1] = acc[mt][ntile][3] * rv1;
        }
    }
    __syncthreads();
    float* zqb = zq_out + (size_t)bb * CC * TT + t0;
    #pragma unroll 8
    for (int i = tid; i < 16384; i += 256) {
        int c = i >> 7, tt = i & 127;
        zqb[(size_t)(c0 + c) * TT + tt] = stage[tt*129 + c];
    }
}

// ---------------------------------------------------------------------------
extern "C" void kernel_launch(void* const* d_in, const int* in_sizes, int n_in,
                              void* d_out, int out_size) {
    (void)in_sizes; (void)n_in;
    const float* z    = (const float*)d_in[0];
    const float* book = (const float*)d_in[1];
    const float* lpq  = (const float*)d_in[2];
    const float* u    = (const float*)d_in[3];
    float* out = (float*)d_out;

    int full = (out_size >= TOTAL_OUT) ? 1 : 0;
    float* zq   = out;
    float* pq   = full ? (out + ZQ_SIZE)    : nullptr;
    float* prob = full ? (pq + 1)           : nullptr;
    float* logp = full ? (prob + PROB_SIZE) : nullptr;
    float* mean = full ? (logp + PROB_SIZE) : nullptr;

    cudaFuncSetAttribute(gemm1,    cudaFuncAttributeMaxDynamicSharedMemorySize, G1_SMEM);
    cudaFuncSetAttribute(gvq_soft, cudaFuncAttributeMaxDynamicSharedMemorySize, SMB_TOT * (int)sizeof(float));
    cudaFuncSetAttribute(gemm2,    cudaFuncAttributeMaxDynamicSharedMemorySize, G2_SMEM);

    bnorm_kernel<<<128, 256>>>(book);
    split_book<<<256, 256>>>(book);
    gemm1<<<256, 256, G1_SMEM>>>(z, lpq);
    gvq_soft<<<NN/SROWS, 256, SMB_TOT * sizeof(float)>>>(u, lpq, prob, logp, pq, full);
    if (full) {
        mp_reduce1<<<32, 256>>>();
        mp_reduce2<<<4, 256>>>(mean);
    }
    gemm2<<<512, 256, G2_SMEM>>>(zq);
}

// round 10
// speedup vs baseline: 4.4399x; 1.3819x over previous
#include <cuda_runtime.h>
#include <cuda_fp16.h>
#include <cstdint>
#include <math.h>

#define BB   8
#define CC   256
#define TT   4096
#define KK   1024
#define NN   (BB*TT)
#define EPSF 1e-10f

#define ZQ_SIZE   (BB*CC*TT)
#define PROB_SIZE (NN*KK)
#define TOTAL_OUT (ZQ_SIZE + 1 + 2*PROB_SIZE + KK)

#define SROWS 16                      // rows per softmax block

// ---------------- device scratch (static — no runtime allocation) ----------
__device__ float    g_bnorm[KK];
__device__ float    g_mp_partial[(NN/SROWS) * KK];     // 8 MB
__device__ float    g_mp2[8 * KK];
__device__ float    g_logits[(size_t)NN * KK];         // 128 MB
__device__ uint32_t g_enc_hi[(size_t)NN * KK / 2];     // 64 MB (fp16x2, [n][512w])
__device__ float    g_rinv[NN];
__device__ uint32_t g_book_hi[KK * CC / 2];            // fp16x2 words, [k][128w]
__device__ uint32_t g_book_lo[KK * CC / 2];
__device__ uint32_t g_bookT_hi[CC * KK / 2];           // fp16x2 words, [c][512w]
__device__ uint32_t g_bookT_lo[CC * KK / 2];

// ---------------- helpers ---------------------------------------------------
__device__ __forceinline__ uint32_t smem_u32(const void* p) {
    uint32_t a;
    asm("{ .reg .u64 t; cvta.to.shared.u64 t, %1; cvt.u32.u64 %0, t; }"
        : "=r"(a) : "l"(p));
    return a;
}
__device__ __forceinline__ void cp16(uint32_t dst, size_t gsrc) {
    asm volatile("cp.async.cg.shared.global [%0], [%1], 16;" :: "r"(dst), "l"(gsrc));
}
#define CP_COMMIT()  asm volatile("cp.async.commit_group;" ::: "memory")
#define CP_WAIT(N)   asm volatile("cp.async.wait_group %0;" :: "n"(N) : "memory")

__device__ __forceinline__ void ldsm4(uint32_t* r, uint32_t addr) {
    asm volatile("ldmatrix.sync.aligned.m8n8.x4.shared.b16 {%0,%1,%2,%3}, [%4];"
        : "=r"(r[0]), "=r"(r[1]), "=r"(r[2]), "=r"(r[3]) : "r"(addr));
}
__device__ __forceinline__ void mma_f16(float* d, const uint32_t* a,
                                        uint32_t b0, uint32_t b1) {
    asm volatile("mma.sync.aligned.m16n8k16.row.col.f32.f16.f16.f32 "
        "{%0,%1,%2,%3}, {%4,%5,%6,%7}, {%8,%9}, {%0,%1,%2,%3};"
        : "+f"(d[0]), "+f"(d[1]), "+f"(d[2]), "+f"(d[3])
        : "r"(a[0]), "r"(a[1]), "r"(a[2]), "r"(a[3]), "r"(b0), "r"(b1));
}
__device__ __forceinline__ uint32_t pack_h2(float a, float b) {
    __half2 t = __floats2half2_rn(a, b);
    return *reinterpret_cast<uint32_t*>(&t);
}
__device__ __forceinline__ float warp_max(float v) {
    #pragma unroll
    for (int o = 16; o > 0; o >>= 1) v = fmaxf(v, __shfl_xor_sync(0xffffffffu, v, o));
    return v;
}
__device__ __forceinline__ float warp_sum(float v) {
    #pragma unroll
    for (int o = 16; o > 0; o >>= 1) v += __shfl_xor_sync(0xffffffffu, v, o);
    return v;
}
__device__ __forceinline__ float gumbelf(float uu) {
    return -__logf(-__logf(uu + EPSF) + EPSF);
}

// ---------------------------------------------------------------------------
// Prep kernels
// ---------------------------------------------------------------------------
__global__ void bnorm_kernel(const float* __restrict__ book) {
    int gw = (blockIdx.x * blockDim.x + threadIdx.x) >> 5;
    int lane = threadIdx.x & 31;
    if (gw >= KK) return;
    const float* row = book + (size_t)gw * CC;
    float s = 0.f;
    #pragma unroll
    for (int c = lane; c < CC; c += 32) { float v = row[c]; s = fmaf(v, v, s); }
    s = warp_sum(s);
    if (lane == 0) g_bnorm[gw] = s;
}

__global__ void split_book(const float* __restrict__ book) {
    __half* bh  = reinterpret_cast<__half*>(g_book_hi);
    __half* bl  = reinterpret_cast<__half*>(g_book_lo);
    __half* bth = reinterpret_cast<__half*>(g_bookT_hi);
    __half* btl = reinterpret_cast<__half*>(g_bookT_lo);
    int idx = blockIdx.x * 256 + threadIdx.x;
    for (int i = idx; i < KK * CC; i += 65536) {
        int k = i >> 8, c = i & 255;
        float v = book[i];
        __half h = __float2half(v);
        __half l = __float2half(v - __half2float(h));
        bh[i] = h; bl[i] = l;
        bth[c * KK + k] = h; btl[c * KK + k] = l;
    }
}

// 2-stage deterministic mean_prob reduction
__global__ void mp_reduce1() {
    int idx = blockIdx.x * 256 + threadIdx.x;     // 32 blocks -> 8192 threads
    int k = idx & 1023, c = idx >> 10;            // c in 0..7
    float s = 0.f;
    #pragma unroll 8
    for (int b = 0; b < (NN/SROWS)/8; ++b)
        s += g_mp_partial[(size_t)(c * ((NN/SROWS)/8) + b) * KK + k];
    g_mp2[c * KK + k] = s;
}
__global__ void mp_reduce2(float* __restrict__ mean_out) {
    int k = blockIdx.x * 256 + threadIdx.x;
    float s = 0.f;
    #pragma unroll
    for (int c = 0; c < 8; ++c) s += g_mp2[c * KK + k];
    mean_out[k] = s;
}

// ---------------------------------------------------------------------------
// GEMM1: logits[n][k] = (2*zhi.(bhi+blo) - |zhi|^2 - |b|^2)*pq  (fp16 2-term)
// |zhi|^2 vs |z|^2: per-row additive constant in logits -> cancels in every
// output (softmax/log-softmax invariance), so hi-only norm is exact-for-outputs.
// 256 blocks x 256 thr; block = 128 rows; book streamed in 64-code chunks,
// cp.async double-buffered.
// smem: zn 0..512 | bn 512..4608 | Ah 4608 (67584) | Bbuf[2] @72192 (2x67584)
// row stride 264 fp16 = 528 B (mult 16; 528 mod 128 = 16 -> ldsm clean)
// ---------------------------------------------------------------------------
#define G1_BBUF  72192
#define G1_BSZ   67584          // per buffer: Bh 33792 + Bl 33792
#define G1_SMEM  207360

__global__ __launch_bounds__(256, 1)
void gemm1(const float* __restrict__ z, const float* __restrict__ lpq) {
    extern __shared__ char smem[];
    float* zn = reinterpret_cast<float*>(smem);
    float* bn = reinterpret_cast<float*>(smem + 512);
    __half* Ah = reinterpret_cast<__half*>(smem + 4608);
    const uint32_t sb = smem_u32(smem);
    const uint32_t Ah_b = sb + 4608;

    const int tid = threadIdx.x, lane = tid & 31, wid = tid >> 5;
    const int blk = blockIdx.x;
    const int n0 = blk * 128;
    const int b  = blk >> 5;
    const int t0 = (blk & 31) * 128;

    const size_t gbh = __cvta_generic_to_global(g_book_hi);
    const size_t gbl = __cvta_generic_to_global(g_book_lo);

    // async fill of B chunk nt into buffer p (overlaps with everything below)
    auto fill_b = [&](int nt, int p) {
        const uint32_t dstb = sb + G1_BBUF + p * G1_BSZ;
        const size_t srcoff = (size_t)(nt * 64) * 512;   // bytes: 64 rows x 512B
        #pragma unroll
        for (int j = 0; j < 8; ++j) {
            int i = j * 256 + tid;          // 0..2047
            int row = i >> 5, f4 = i & 31;
            uint32_t d = dstb + row * 528 + f4 * 16;
            size_t s = srcoff + (size_t)row * 512 + f4 * 16;
            cp16(d,         gbh + s);
            cp16(d + 33792, gbl + s);
        }
    };

    fill_b(0, 0);
    CP_COMMIT();

    for (int i = tid; i < KK; i += 256) bn[i] = g_bnorm[i];

    // ---- A fill (hi only): thread = channel c, rows = t ----
    {
        const float* zp = z + (size_t)b * CC * TT + (size_t)tid * TT + t0;
        #pragma unroll 4
        for (int i = 0; i < 32; ++i) {
            float4 v = *reinterpret_cast<const float4*>(zp + 4*i);
            Ah[(4*i+0)*264 + tid] = __float2half(v.x);
            Ah[(4*i+1)*264 + tid] = __float2half(v.y);
            Ah[(4*i+2)*264 + tid] = __float2half(v.z);
            Ah[(4*i+3)*264 + tid] = __float2half(v.w);
        }
    }
    __syncthreads();

    // ---- z row norms from fp16-hi (output-exact; see header comment) ----
    for (int rr = 0; rr < 16; ++rr) {
        int r = wid * 16 + rr;
        float s = 0.f;
        #pragma unroll
        for (int c = lane; c < CC; c += 32) {
            float v = __half2float(Ah[r*264 + c]);
            s = fmaf(v, v, s);
        }
        s = warp_sum(s);
        if (lane == 0) zn[r] = s;
    }

    const float pqv = 0.5f / (1.0f + expf(lpq[0]));

    const int wm = wid >> 1, wn = wid & 1;
    const int r0w = wm * 32, n0w = wn * 32;
    const int g = lane >> 2, tig = lane & 3;
    const int arow  = (lane & 7) + ((lane >> 3) & 1) * 8;
    const int akoff = (lane >> 4) * 8;
    const int brow  = (lane & 7) + (lane >> 4) * 8;
    const int bkoff = ((lane >> 3) & 1) * 8;

    for (int nt = 0; nt < 16; ++nt) {
        if (nt + 1 < 16) {
            fill_b(nt + 1, (nt + 1) & 1);
            CP_COMMIT();
            CP_WAIT(1);
        } else {
            CP_WAIT(0);
        }
        __syncthreads();

        const uint32_t Bh_b = sb + G1_BBUF + (nt & 1) * G1_BSZ;
        const uint32_t Bl_b = Bh_b + 33792;

        float acc[2][4][4];
        #pragma unroll
        for (int i = 0; i < 2; ++i)
            #pragma unroll
            for (int j = 0; j < 4; ++j)
                #pragma unroll
                for (int e = 0; e < 4; ++e) acc[i][j][e] = 0.f;

        #pragma unroll 2
        for (int ks = 0; ks < 16; ++ks) {
            uint32_t af[2][4], bf[2][4], blf[2][4];
            #pragma unroll
            for (int mt = 0; mt < 2; ++mt) {
                uint32_t off = (uint32_t)((r0w + mt*16 + arow) * 264 + ks*16 + akoff) * 2;
                ldsm4(af[mt], Ah_b + off);
            }
            #pragma unroll
            for (int np = 0; np < 2; ++np) {
                uint32_t off = (uint32_t)((n0w + np*16 + brow) * 264 + ks*16 + bkoff) * 2;
                ldsm4(bf[np],  Bh_b + off);
                ldsm4(blf[np], Bl_b + off);
            }
            #pragma unroll
            for (int mt = 0; mt < 2; ++mt)
                #pragma unroll
                for (int ntile = 0; ntile < 4; ++ntile) {
                    int np = ntile >> 1, sub = (ntile & 1) * 2;
                    mma_f16(acc[mt][ntile], af[mt], bf[np][sub],  bf[np][sub+1]);
                    mma_f16(acc[mt][ntile], af[mt], blf[np][sub], blf[np][sub+1]);
                }
        }

        // epilogue: scale + direct float2 stores to g_logits
        #pragma unroll
        for (int mt = 0; mt < 2; ++mt) {
            int r_lo = r0w + mt*16 + g;
            float zn0 = zn[r_lo], zn1 = zn[r_lo + 8];
            #pragma unroll
            for (int ntile = 0; ntile < 4; ++ntile) {
                int col = nt*64 + n0w + ntile*8 + 2*tig;
                float bn0 = bn[col], bn1 = bn[col + 1];
                float2 w0, w1;
                w0.x = (2.f*acc[mt][ntile][0] - zn0 - bn0) * pqv;
                w0.y = (2.f*acc[mt][ntile][1] - zn0 - bn1) * pqv;
                w1.x = (2.f*acc[mt][ntile][2] - zn1 - bn0) * pqv;
                w1.y = (2.f*acc[mt][ntile][3] - zn1 - bn1) * pqv;
                *reinterpret_cast<float2*>(&g_logits[(size_t)(n0 + r_lo) * KK + col]) = w0;
                *reinterpret_cast<float2*>(&g_logits[(size_t)(n0 + r_lo + 8) * KK + col]) = w1;
            }
        }
        __syncthreads();
    }
}

// ---------------------------------------------------------------------------
// Softmax kernel: prob/log_prob/mean partials + Gumbel-exp -> enc (fp16 hi)
// 2048 blocks x 256 thr; block = 16 rows; L in smem (64 KB) -> 2 CTAs/SM
// ---------------------------------------------------------------------------
#define SMB_TOT  (SROWS * KK + 16)

__global__ __launch_bounds__(256, 2)
void gvq_soft(const float* __restrict__ u, const float* __restrict__ lpq,
              float* __restrict__ prob_out, float* __restrict__ logp_out,
              float* __restrict__ pq_out, int full)
{
    extern __shared__ float sm[];
    float* L  = sm;
    float* ra = sm + SROWS * KK;

    const int tid = threadIdx.x, blk = blockIdx.x;
    const int n0 = blk * SROWS;
    const int lane = tid & 31, warp = tid >> 5;

    if (full && blk == 0 && tid == 0)
        *pq_out = 0.5f / (1.0f + expf(lpq[0]));

    #pragma unroll
    for (int it = 0; it < 16; ++it) {
        int idx = it * 256 + tid;
        int r = idx >> 8, kw = idx & 255;
        *reinterpret_cast<float4*>(&L[r * KK + kw * 4]) =
            *reinterpret_cast<const float4*>(&g_logits[(size_t)(n0 + r) * KK + kw * 4]);
    }
    __syncthreads();

    if (full) {
        #pragma unroll
        for (int rr = 0; rr < 2; ++rr) {
            int r = warp * 2 + rr;
            const float* Lr = L + r * KK;
            float m = __int_as_float(0xff800000);
            #pragma unroll
            for (int kb = 0; kb < 8; ++kb) {
                float4 v = *reinterpret_cast<const float4*>(Lr + kb*128 + lane*4);
                m = fmaxf(m, fmaxf(fmaxf(v.x, v.y), fmaxf(v.z, v.w)));
            }
            m = warp_max(m);
            float s = 0.f;
            #pragma unroll
            for (int kb = 0; kb < 8; ++kb) {
                float4 v = *reinterpret_cast<const float4*>(Lr + kb*128 + lane*4);
                s += __expf(v.x - m) + __expf(v.y - m) + __expf(v.z - m) + __expf(v.w - m);
            }
            s = warp_sum(s);
            if (lane == 0) ra[r] = m + __logf(s);
        }
        __syncthreads();

        const float invN = 1.0f / (float)NN;
        #pragma unroll
        for (int j = 0; j < 4; ++j) {
            int k = tid + j * 256;
            float mp = 0.f;
            #pragma unroll 8
            for (int r = 0; r < SROWS; ++r) {
                float lp = L[r * KK + k] - ra[r];
                float p  = __expf(lp);
                prob_out[(size_t)(n0 + r) * KK + k] = p;
                logp_out[(size_t)(n0 + r) * KK + k] = lp;
                mp += p;
            }
            g_mp_partial[(size_t)blk * KK + k] = mp * invN;
        }
        __syncthreads();
    }

    // Gumbel + temperature-0.5 softmax; emit unnormalized exp as fp16 (hi only)
    #pragma unroll
    for (int rr = 0; rr < 2; ++rr) {
        int r = warp * 2 + rr;
        const float* ur = u + (size_t)(n0 + r) * KK;
        float* Lr = L + r * KK;
        float m = __int_as_float(0xff800000);
        #pragma unroll
        for (int kb = 0; kb < 8; ++kb) {
            float4 uv = *reinterpret_cast<const float4*>(ur + kb*128 + lane*4);
            float4 lv = *reinterpret_cast<float4*>(Lr + kb*128 + lane*4);
            lv.x += gumbelf(uv.x); lv.y += gumbelf(uv.y);
            lv.z += gumbelf(uv.z); lv.w += gumbelf(uv.w);
            *reinterpret_cast<float4*>(Lr + kb*128 + lane*4) = lv;
            m = fmaxf(m, fmaxf(fmaxf(lv.x, lv.y), fmaxf(lv.z, lv.w)));
        }
        m = warp_max(m);
        float s = 0.f;
        #pragma unroll
        for (int kb = 0; kb < 8; ++kb) {
            float4 lv = *reinterpret_cast<float4*>(Lr + kb*128 + lane*4);
            float e0 = __expf(2.0f * (lv.x - m));
            float e1 = __expf(2.0f * (lv.y - m));
            float e2 = __expf(2.0f * (lv.z - m));
            float e3 = __expf(2.0f * (lv.w - m));
            s += e0 + e1 + e2 + e3;
            uint2 hv;
            hv.x = pack_h2(e0, e1);
            hv.y = pack_h2(e2, e3);
            reinterpret_cast<uint2*>(g_enc_hi)[(size_t)(n0 + r) * 256 + kb * 32 + lane] = hv;
        }
        s = warp_sum(s);
        if (lane == 0) g_rinv[n0 + r] = 1.0f / s;
    }
}

// ---------------------------------------------------------------------------
// GEMM2: z_q = (ehi @ (bhi+blo)) * rinv  (fp16 2-term), cp.async double-buffer
// 512 blocks: blk>>1 = 128-row tile, blk&1 = 128-c half. k streamed in 64s.
// smem: rinv 0..512 | buf[2] @512: A 18432 + Bh 18432 + Bl 18432 = 55296 each
// tile row stride 72 fp16 = 144 B; stage (66048) reuses buffer space at 512
// ---------------------------------------------------------------------------
#define G2_BUF   512
#define G2_BSZ   55296
#define G2_SMEM  111104

__global__ __launch_bounds__(256, 2)
void gemm2(float* __restrict__ zq_out) {
    extern __shared__ char smem[];
    float* rinv_s = reinterpret_cast<float*>(smem);
    const uint32_t sb = smem_u32(smem);

    const int tid = threadIdx.x, lane = tid & 31, wid = tid >> 5;
    const int blk = blockIdx.x;
    const int rt = blk >> 1, ch = blk & 1;
    const int n0 = rt * 128;
    const int c0 = ch * 128;
    const int bb = rt >> 5;
    const int t0 = (rt & 31) * 128;

    const size_t geh = __cvta_generic_to_global(g_enc_hi);
    const size_t gth = __cvta_generic_to_global(g_bookT_hi);
    const size_t gtl = __cvta_generic_to_global(g_bookT_lo);

    auto fill = [&](int kc, int p) {
        const uint32_t dstb = sb + G2_BUF + p * G2_BSZ;
        #pragma unroll
        for (int j = 0; j < 4; ++j) {
            int i = j * 256 + tid;           // 0..1023
            int row = i >> 3, f4 = i & 7;
            uint32_t d = dstb + row * 144 + f4 * 16;
            // A: enc hi rows n0+row
            cp16(d, geh + (size_t)(n0 + row) * 2048 + kc * 128 + f4 * 16);
            // B: bookT hi/lo rows c0+row
            size_t bsrc = (size_t)(c0 + row) * 2048 + kc * 128 + f4 * 16;
            cp16(d + 18432, gth + bsrc);
            cp16(d + 36864, gtl + bsrc);
        }
    };

    fill(0, 0);
    CP_COMMIT();

    if (tid < 128) rinv_s[tid] = g_rinv[n0 + tid];

    const int wm = wid >> 2, wn = wid & 3;
    const int r0w = wm * 64, n0w = wn * 32;
    const int g = lane >> 2, tig = lane & 3;
    const int arow  = (lane & 7) + ((lane >> 3) & 1) * 8;
    const int akoff = (lane >> 4) * 8;
    const int brow  = (lane & 7) + (lane >> 4) * 8;
    const int bkoff = ((lane >> 3) & 1) * 8;

    float acc[4][4][4];
    #pragma unroll
    for (int i = 0; i < 4; ++i)
        #pragma unroll
        for (int j = 0; j < 4; ++j)
            #pragma unroll
            for (int e = 0; e < 4; ++e) acc[i][j][e] = 0.f;

    for (int kc = 0; kc < 16; ++kc) {
        if (kc + 1 < 16) {
            fill(kc + 1, (kc + 1) & 1);
            CP_COMMIT();
            CP_WAIT(1);
        } else {
            CP_WAIT(0);
        }
        __syncthreads();

        const uint32_t Ah_b = sb + G2_BUF + (kc & 1) * G2_BSZ;
        const uint32_t Bh_b = Ah_b + 18432, Bl_b = Ah_b + 36864;

        #pragma unroll
        for (int ks = 0; ks < 4; ++ks) {
            uint32_t af[4][4], bf[2][4], blf[2][4];
            #pragma unroll
            for (int mt = 0; mt < 4; ++mt) {
                uint32_t off = (uint32_t)((r0w + mt*16 + arow) * 72 + ks*16 + akoff) * 2;
                ldsm4(af[mt], Ah_b + off);
            }
            #pragma unroll
            for (int np = 0; np < 2; ++np) {
                uint32_t off = (uint32_t)((n0w + np*16 + brow) * 72 + ks*16 + bkoff) * 2;
                ldsm4(bf[np],  Bh_b + off);
                ldsm4(blf[np], Bl_b + off);
            }
            #pragma unroll
            for (int mt = 0; mt < 4; ++mt)
                #pragma unroll
                for (int ntile = 0; ntile < 4; ++ntile) {
                    int np = ntile >> 1, sub = (ntile & 1) * 2;
                    mma_f16(acc[mt][ntile], af[mt], bf[np][sub],  bf[np][sub+1]);
                    mma_f16(acc[mt][ntile], af[mt], blf[np][sub], blf[np][sub+1]);
                }
        }
        __syncthreads();
    }

    // ---- epilogue: scale by rinv, stage [t][c] (pad 129), coalesced write ----
    float* stage = reinterpret_cast<float*>(smem + G2_BUF);
    #pragma unroll
    for (int mt = 0; mt < 4; ++mt) {
        int t_lo = r0w + mt*16 + g;
        float rv0 = rinv_s[t_lo], rv1 = rinv_s[t_lo + 8];
        #pragma unroll
        for (int ntile = 0; ntile < 4; ++ntile) {
            int c = n0w + ntile*8 + 2*tig;
            stage[t_lo*129 + c]       = acc[mt][ntile][0] * rv0;
            stage[t_lo*129 + c + 1]   = acc[mt][ntile][1] * rv0;
            stage[(t_lo+8)*129 + c]   = acc[mt][ntile][2] * rv1;
            stage[(t_lo+8)*129 + c+1] = acc[mt][ntile][3] * rv1;
        }
    }
    __syncthreads();
    float* zqb = zq_out + (size_t)bb * CC * TT + t0;
    #pragma unroll 8
    for (int i = tid; i < 16384; i += 256) {
        int c = i >> 7, tt = i & 127;
        zqb[(size_t)(c0 + c) * TT + tt] = stage[tt*129 + c];
    }
}

// ---------------------------------------------------------------------------
extern "C" void kernel_launch(void* const* d_in, const int* in_sizes, int n_in,
                              void* d_out, int out_size) {
    (void)in_sizes; (void)n_in;
    const float* z    = (const float*)d_in[0];
    const float* book = (const float*)d_in[1];
    const float* lpq  = (const float*)d_in[2];
    const float* u    = (const float*)d_in[3];
    float* out = (float*)d_out;

    int full = (out_size >= TOTAL_OUT) ? 1 : 0;
    float* zq   = out;
    float* pq   = full ? (out + ZQ_SIZE)    : nullptr;
    float* prob = full ? (pq + 1)           : nullptr;
    float* logp = full ? (prob + PROB_SIZE) : nullptr;
    float* mean = full ? (logp + PROB_SIZE) : nullptr;

    cudaFuncSetAttribute(gemm1,    cudaFuncAttributeMaxDynamicSharedMemorySize, G1_SMEM);
    cudaFuncSetAttribute(gvq_soft, cudaFuncAttributeMaxDynamicSharedMemorySize, SMB_TOT * (int)sizeof(float));
    cudaFuncSetAttribute(gemm2,    cudaFuncAttributeMaxDynamicSharedMemorySize, G2_SMEM);

    bnorm_kernel<<<128, 256>>>(book);
    split_book<<<256, 256>>>(book);
    gemm1<<<256, 256, G1_SMEM>>>(z, lpq);
    gvq_soft<<<NN/SROWS, 256, SMB_TOT * sizeof(float)>>>(u, lpq, prob, logp, pq, full);
    if (full) {
        mp_reduce1<<<32, 256>>>();
        mp_reduce2<<<4, 256>>>(mean);
    }
    gemm2<<<512, 256, G2_SMEM>>>(zq);
}